// round 9
// baseline (speedup 1.0000x reference)
#include <cuda_runtime.h>
#include <math.h>

// ============================================================================
// 3-kernel ImplicitMLP (round-8 structure, occupancy bump):
//  K1: GFF + rank contract warp-tiled GEMM.  TPB 384->512 (16 warps, 128-reg
//      cap; live set measured 124 in round 8 -> fits).
//  K2: layer-1 expand GEMM + bias/ReLU/R2 contract. TPB 384->448 (14 warps,
//      146-reg cap; 512 impossible: u-tiles would exceed 227KB smem).
//  K3: layer-2 expand + dense tail (unchanged).
// ============================================================================

#define NPTS_C  524288
#define K1_TPB  512
#define K2_TPB  448
#define K3_TPB  512

typedef unsigned long long u64;

__device__ u64 g_u[40 * (size_t)NPTS_C];   // rank-pair major, point minor
__device__ u64 g_w[5 * (size_t)NPTS_C];    // j-pair major, point minor

__device__ __forceinline__ u64 f2fma(u64 a, u64 b, u64 c) {
    u64 d;
    asm("fma.rn.f32x2 %0, %1, %2, %3;" : "=l"(d) : "l"(a), "l"(b), "l"(c));
    return d;
}
__device__ __forceinline__ u64 f2add(u64 a, u64 b) {
    u64 d;
    asm("add.rn.f32x2 %0, %1, %2;" : "=l"(d) : "l"(a), "l"(b));
    return d;
}
__device__ __forceinline__ u64 pack2(float lo, float hi) {
    u64 r;
    asm("mov.b64 %0, {%1, %2};" : "=l"(r) : "f"(lo), "f"(hi));
    return r;
}
__device__ __forceinline__ float2 unpack2(u64 v) {
    float lo, hi;
    asm("mov.b64 {%0, %1}, %2;" : "=f"(lo), "=f"(hi) : "l"(v));
    return make_float2(lo, hi);
}

// ---------------------------------------------------------------------------
// Kernel 1 (GEMM form): ranks padded to 72 (4 og x 18 = 9 pairs each).
// ---------------------------------------------------------------------------
#define G1_BP   0
#define G1_WR   256
#define G1_OGS  4616                      // 256*18 + 8 skew (bank decorrelate)
#define G1_F    (G1_BP + 256 + 4 * G1_OGS)          // 18720
#define K1_SMEM (G1_F + (K1_TPB / 32) * 1024)       // 18720 + 16384 = 35104 f32

__global__ void __launch_bounds__(K1_TPB, 1) gff_contract_kernel(
    const float* __restrict__ coords, const float* __restrict__ Bmat,
    const float* __restrict__ R1, int npts)
{
    extern __shared__ float sm[];
    const int tid = threadIdx.x;
    const float TWOPI = 6.283185307179586f;

    for (int i = tid; i < 128; i += K1_TPB) {
        sm[G1_BP + 2 * i]     = Bmat[i] * TWOPI;
        sm[G1_BP + 2 * i + 1] = Bmat[128 + i] * TWOPI;
    }
    for (int idx = tid; idx < 4 * 256 * 18; idx += K1_TPB) {
        int og  = idx / 4608;
        int rem = idx - og * 4608;
        int k   = rem / 18;
        int jj  = rem - k * 18;
        int i   = k >> 1;
        int r   = og * 18 + jj;
        float v = 0.f;
        if (r < 70) v = R1[r * 256 + ((k & 1) ? 128 : 0) + i];
        sm[G1_WR + og * G1_OGS + k * 18 + jj] = v;
    }
    __syncthreads();

    const int wid  = tid >> 5;
    const int lane = tid & 31;
    const int pg   = lane & 7;
    const int og   = lane >> 3;
    float* F = &sm[G1_F + wid * 1024];
    const float* wrbase = &sm[G1_WR + og * G1_OGS];

    const int ntiles = npts >> 5;
    const int gw = blockIdx.x * (K1_TPB / 32) + wid;
    const int nw = gridDim.x * (K1_TPB / 32);

    for (int t = gw; t < ntiles; t += nw) {
        const int pt = (t << 5) + lane;
        const int b  = pt >> 12, hw = pt & 4095;
        const float c0 = coords[b * 8192 + hw];
        const float c1 = coords[b * 8192 + 4096 + hw];

        u64 acc[4][9];
        #pragma unroll
        for (int p = 0; p < 4; p++)
            #pragma unroll
            for (int j = 0; j < 9; j++) acc[p][j] = 0ull;

        #pragma unroll 1
        for (int ch = 0; ch < 8; ch++) {
            #pragma unroll
            for (int ii = 0; ii < 16; ii++) {
                float2 bv = reinterpret_cast<const float2*>(&sm[G1_BP])[ch * 16 + ii];
                float pr = fmaf(c0, bv.x, c1 * bv.y);
                float s, c;
                __sincosf(pr, &s, &c);
                F[(2 * ii) * 32 + lane]     = s;
                F[(2 * ii + 1) * 32 + lane] = c;
            }
            __syncwarp();

            const float* wk = &wrbase[(ch * 32) * 18];
            #pragma unroll 2
            for (int kk = 0; kk < 32; kk++) {
                float4 uv = *reinterpret_cast<const float4*>(&F[kk * 32 + pg * 4]);
                const u64* wr = reinterpret_cast<const u64*>(&wk[kk * 18]);
                u64 w0 = wr[0], w1 = wr[1], w2 = wr[2], w3 = wr[3], w4 = wr[4];
                u64 w5 = wr[5], w6 = wr[6], w7 = wr[7], w8 = wr[8];
                u64 d0 = pack2(uv.x, uv.x);
                u64 d1 = pack2(uv.y, uv.y);
                u64 d2 = pack2(uv.z, uv.z);
                u64 d3 = pack2(uv.w, uv.w);
                acc[0][0] = f2fma(d0, w0, acc[0][0]);
                acc[0][1] = f2fma(d0, w1, acc[0][1]);
                acc[0][2] = f2fma(d0, w2, acc[0][2]);
                acc[0][3] = f2fma(d0, w3, acc[0][3]);
                acc[0][4] = f2fma(d0, w4, acc[0][4]);
                acc[0][5] = f2fma(d0, w5, acc[0][5]);
                acc[0][6] = f2fma(d0, w6, acc[0][6]);
                acc[0][7] = f2fma(d0, w7, acc[0][7]);
                acc[0][8] = f2fma(d0, w8, acc[0][8]);
                acc[1][0] = f2fma(d1, w0, acc[1][0]);
                acc[1][1] = f2fma(d1, w1, acc[1][1]);
                acc[1][2] = f2fma(d1, w2, acc[1][2]);
                acc[1][3] = f2fma(d1, w3, acc[1][3]);
                acc[1][4] = f2fma(d1, w4, acc[1][4]);
                acc[1][5] = f2fma(d1, w5, acc[1][5]);
                acc[1][6] = f2fma(d1, w6, acc[1][6]);
                acc[1][7] = f2fma(d1, w7, acc[1][7]);
                acc[1][8] = f2fma(d1, w8, acc[1][8]);
                acc[2][0] = f2fma(d2, w0, acc[2][0]);
                acc[2][1] = f2fma(d2, w1, acc[2][1]);
                acc[2][2] = f2fma(d2, w2, acc[2][2]);
                acc[2][3] = f2fma(d2, w3, acc[2][3]);
                acc[2][4] = f2fma(d2, w4, acc[2][4]);
                acc[2][5] = f2fma(d2, w5, acc[2][5]);
                acc[2][6] = f2fma(d2, w6, acc[2][6]);
                acc[2][7] = f2fma(d2, w7, acc[2][7]);
                acc[2][8] = f2fma(d2, w8, acc[2][8]);
                acc[3][0] = f2fma(d3, w0, acc[3][0]);
                acc[3][1] = f2fma(d3, w1, acc[3][1]);
                acc[3][2] = f2fma(d3, w2, acc[3][2]);
                acc[3][3] = f2fma(d3, w3, acc[3][3]);
                acc[3][4] = f2fma(d3, w4, acc[3][4]);
                acc[3][5] = f2fma(d3, w5, acc[3][5]);
                acc[3][6] = f2fma(d3, w6, acc[3][6]);
                acc[3][7] = f2fma(d3, w7, acc[3][7]);
                acc[3][8] = f2fma(d3, w8, acc[3][8]);
            }
            __syncwarp();
        }

        const int p32 = t << 5;
        #pragma unroll
        for (int j = 0; j < 9; j++) {
            u64* grow = &g_u[(size_t)(og * 9 + j) * NPTS_C + p32 + pg * 4];
            #pragma unroll
            for (int p = 0; p < 4; p++) grow[p] = acc[p][j];
        }
    }
}

// ---------------------------------------------------------------------------
// Kernel 2: layer-1 expand GEMM + bias + ReLU + R2 contract.
// ---------------------------------------------------------------------------
#define S_L1K 0
#define S_R2  (72 * 256)
#define S_B1  (S_R2 + 256 * 12)
#define S_UT  (S_B1 + 256)
#define K2_SMEM (S_UT + (K2_TPB / 32) * 72 * 32)   // 21760 + 14*2304 = 54016 f32

__global__ void __launch_bounds__(K2_TPB, 1) expand_contract_kernel(
    const float* __restrict__ L1, const float* __restrict__ b1,
    const float* __restrict__ R2, int npts)
{
    extern __shared__ float sm[];
    const int tid = threadIdx.x;

    for (int idx = tid; idx < 72 * 256; idx += K2_TPB) {
        int k = idx >> 8, o = idx & 255;
        sm[S_L1K + idx] = (k < 70) ? L1[o * 70 + k] : 0.f;
    }
    for (int idx = tid; idx < 256 * 12; idx += K2_TPB) {
        int o = idx / 12, j = idx - o * 12;
        sm[S_R2 + idx] = (j < 10) ? R2[j * 256 + o] : 0.f;
    }
    for (int i = tid; i < 256; i += K2_TPB) sm[S_B1 + i] = b1[i];
    __syncthreads();

    const int wid  = tid >> 5;
    const int lane = tid & 31;
    const int pg   = lane & 7;
    const int og   = lane >> 3;
    float* su = &sm[S_UT + wid * (72 * 32)];

    const int ntiles = npts >> 5;
    const int gw = blockIdx.x * (K2_TPB / 32) + wid;
    const int nw = gridDim.x * (K2_TPB / 32);

    for (int t = gw; t < ntiles; t += nw) {
        const int p32 = t << 5;

        __syncwarp();
        #pragma unroll 4
        for (int rp = 0; rp < 36; rp++) {
            u64 v = g_u[(size_t)rp * NPTS_C + p32 + lane];
            float2 f = unpack2(v);
            su[(2 * rp) * 32 + lane]     = f.x;
            su[(2 * rp + 1) * 32 + lane] = f.y;
        }
        __syncwarp();

        u64 wpart[4][5];
        #pragma unroll
        for (int p = 0; p < 4; p++)
            #pragma unroll
            for (int jp = 0; jp < 5; jp++) wpart[p][jp] = 0ull;

        #pragma unroll 1
        for (int pass = 0; pass < 8; pass++) {
            const int ob = pass * 32 + og * 8;

            u64 acc[4][4];
            #pragma unroll
            for (int p = 0; p < 4; p++)
                #pragma unroll
                for (int op = 0; op < 4; op++) acc[p][op] = 0ull;

            const float* wbase = &sm[S_L1K + ob];
            const float* ubase = &su[pg * 4];

            #pragma unroll 4
            for (int k = 0; k < 72; k++) {
                float4 uv = *reinterpret_cast<const float4*>(&ubase[k * 32]);
                ulonglong2 w01 = *reinterpret_cast<const ulonglong2*>(&wbase[k * 256]);
                ulonglong2 w23 = *reinterpret_cast<const ulonglong2*>(&wbase[k * 256 + 4]);
                u64 d0 = pack2(uv.x, uv.x);
                u64 d1 = pack2(uv.y, uv.y);
                u64 d2 = pack2(uv.z, uv.z);
                u64 d3 = pack2(uv.w, uv.w);
                acc[0][0] = f2fma(d0, w01.x, acc[0][0]);
                acc[0][1] = f2fma(d0, w01.y, acc[0][1]);
                acc[0][2] = f2fma(d0, w23.x, acc[0][2]);
                acc[0][3] = f2fma(d0, w23.y, acc[0][3]);
                acc[1][0] = f2fma(d1, w01.x, acc[1][0]);
                acc[1][1] = f2fma(d1, w01.y, acc[1][1]);
                acc[1][2] = f2fma(d1, w23.x, acc[1][2]);
                acc[1][3] = f2fma(d1, w23.y, acc[1][3]);
                acc[2][0] = f2fma(d2, w01.x, acc[2][0]);
                acc[2][1] = f2fma(d2, w01.y, acc[2][1]);
                acc[2][2] = f2fma(d2, w23.x, acc[2][2]);
                acc[2][3] = f2fma(d2, w23.y, acc[2][3]);
                acc[3][0] = f2fma(d3, w01.x, acc[3][0]);
                acc[3][1] = f2fma(d3, w01.y, acc[3][1]);
                acc[3][2] = f2fma(d3, w23.x, acc[3][2]);
                acc[3][3] = f2fma(d3, w23.y, acc[3][3]);
            }

            const ulonglong2* bp2 = reinterpret_cast<const ulonglong2*>(&sm[S_B1 + ob]);
            ulonglong2 bA = bp2[0], bB = bp2[1];
            u64 bias[4] = { bA.x, bA.y, bB.x, bB.y };

            #pragma unroll
            for (int op = 0; op < 4; op++) {
                const u64* r0 = reinterpret_cast<const u64*>(&sm[S_R2 + (ob + 2 * op) * 12]);
                const u64* r1 = reinterpret_cast<const u64*>(&sm[S_R2 + (ob + 2 * op + 1) * 12]);
                u64 q0[5], q1[5];
                #pragma unroll
                for (int jp = 0; jp < 5; jp++) { q0[jp] = r0[jp]; q1[jp] = r1[jp]; }
                #pragma unroll
                for (int p = 0; p < 4; p++) {
                    float2 h = unpack2(f2add(acc[p][op], bias[op]));
                    float hx = fmaxf(h.x, 0.f);
                    float hy = fmaxf(h.y, 0.f);
                    u64 dx = pack2(hx, hx);
                    u64 dy = pack2(hy, hy);
                    #pragma unroll
                    for (int jp = 0; jp < 5; jp++)
                        wpart[p][jp] = f2fma(dx, q0[jp],
                                       f2fma(dy, q1[jp], wpart[p][jp]));
                }
            }
        }

        #pragma unroll
        for (int p = 0; p < 4; p++)
            #pragma unroll
            for (int jp = 0; jp < 5; jp++) {
                u64 v = wpart[p][jp];
                v = f2add(v, __shfl_xor_sync(0xffffffffu, v, 8));
                v = f2add(v, __shfl_xor_sync(0xffffffffu, v, 16));
                wpart[p][jp] = v;
            }

        const int myp = p32 + pg * 4 + og;
        #pragma unroll
        for (int jp = 0; jp < 5; jp++)
            g_w[(size_t)jp * NPTS_C + myp] = wpart[og][jp];
    }
}

// ---------------------------------------------------------------------------
// Kernel 3: layer-2 expand + dense tail, 2 points/thread (unchanged).
// ---------------------------------------------------------------------------
#define T_L2 0
#define T_W3 (128 * 12)
#define T_W4 (T_W3 + 128 * 32)
#define T_W5 (T_W4 + 32 * 16)
#define T_B2 (T_W5 + 16 * 4)
#define T_B3 (T_B2 + 128)
#define T_B4 (T_B3 + 32)
#define T_B5 (T_B4 + 16)
#define K3_SMEM (T_B5 + 4)

__global__ void __launch_bounds__(K3_TPB, 1) tail_kernel(
    const float* __restrict__ L2, const float* __restrict__ b2,
    const float* __restrict__ W3, const float* __restrict__ b3,
    const float* __restrict__ W4, const float* __restrict__ b4,
    const float* __restrict__ W5, const float* __restrict__ b5,
    float* __restrict__ out, int npts)
{
    extern __shared__ float sm[];
    const int tid = threadIdx.x;

    for (int idx = tid; idx < 128 * 12; idx += K3_TPB) {
        int o = idx / 12, j = idx - o * 12;
        sm[T_L2 + idx] = (j < 10) ? L2[o * 10 + j] : 0.f;
    }
    for (int idx = tid; idx < 128 * 32; idx += K3_TPB) {
        int o = idx / 32, k = idx - o * 32;
        sm[T_W3 + idx] = W3[k * 128 + o];
    }
    for (int idx = tid; idx < 32 * 16; idx += K3_TPB) {
        int k = idx / 16, q = idx - k * 16;
        sm[T_W4 + idx] = W4[q * 32 + k];
    }
    for (int idx = tid; idx < 16 * 4; idx += K3_TPB) {
        int q = idx / 4, c = idx - q * 4;
        sm[T_W5 + idx] = (c < 3) ? W5[c * 16 + q] : 0.f;
    }
    for (int i = tid; i < 128; i += K3_TPB) sm[T_B2 + i] = b2[i];
    for (int i = tid; i < 32;  i += K3_TPB) sm[T_B3 + i] = b3[i];
    for (int i = tid; i < 16;  i += K3_TPB) sm[T_B4 + i] = b4[i];
    if (tid < 4) sm[T_B5 + tid] = (tid < 3) ? b5[tid] : 0.f;
    __syncthreads();

    const int NT = gridDim.x * K3_TPB;
    const int stride2 = 2 * NT;

    for (int p0 = blockIdx.x * K3_TPB + tid; p0 < npts; p0 += stride2) {
        const int p1 = p0 + NT;
        const bool has1 = (p1 < npts);
        const int p1c = has1 ? p1 : p0;

        u64 wa[6], wb[6];
        #pragma unroll
        for (int jp = 0; jp < 5; jp++) {
            wa[jp] = g_w[(size_t)jp * NPTS_C + p0];
            wb[jp] = g_w[(size_t)jp * NPTS_C + p1c];
        }
        wa[5] = 0ull; wb[5] = 0ull;

        u64 h3a[16], h3b[16];
        #pragma unroll
        for (int k = 0; k < 16; k++) { h3a[k] = 0ull; h3b[k] = 0ull; }

        for (int o = 0; o < 128; o++) {
            const ulonglong2* l2r = reinterpret_cast<const ulonglong2*>(&sm[T_L2 + o * 12]);
            ulonglong2 q0 = l2r[0], q1 = l2r[1], q2 = l2r[2];
            u64 aa = f2fma(wa[0], q0.x, 0ull);
            u64 ab = f2fma(wb[0], q0.x, 0ull);
            aa = f2fma(wa[1], q0.y, aa);  ab = f2fma(wb[1], q0.y, ab);
            aa = f2fma(wa[2], q1.x, aa);  ab = f2fma(wb[2], q1.x, ab);
            aa = f2fma(wa[3], q1.y, aa);  ab = f2fma(wb[3], q1.y, ab);
            aa = f2fma(wa[4], q2.x, aa);  ab = f2fma(wb[4], q2.x, ab);
            aa = f2fma(wa[5], q2.y, aa);  ab = f2fma(wb[5], q2.y, ab);
            float bias2 = sm[T_B2 + o];
            float2 va = unpack2(aa);
            float2 vb = unpack2(ab);
            float ha = fmaxf(va.x + va.y + bias2, 0.f);
            float hb = fmaxf(vb.x + vb.y + bias2, 0.f);
            u64 hha = pack2(ha, ha);
            u64 hhb = pack2(hb, hb);
            const ulonglong2* w3r = reinterpret_cast<const ulonglong2*>(&sm[T_W3 + o * 32]);
            #pragma unroll
            for (int k = 0; k < 8; k++) {
                ulonglong2 v = w3r[k];
                h3a[2 * k]     = f2fma(hha, v.x, h3a[2 * k]);
                h3a[2 * k + 1] = f2fma(hha, v.y, h3a[2 * k + 1]);
                h3b[2 * k]     = f2fma(hhb, v.x, h3b[2 * k]);
                h3b[2 * k + 1] = f2fma(hhb, v.y, h3b[2 * k + 1]);
            }
        }

        float v3a[32], v3b[32];
        #pragma unroll
        for (int k = 0; k < 16; k++) {
            float b3lo = sm[T_B3 + 2 * k], b3hi = sm[T_B3 + 2 * k + 1];
            float2 xa = unpack2(h3a[k]);
            float2 xb = unpack2(h3b[k]);
            v3a[2 * k]     = fmaxf(xa.x + b3lo, 0.f);
            v3a[2 * k + 1] = fmaxf(xa.y + b3hi, 0.f);
            v3b[2 * k]     = fmaxf(xb.x + b3lo, 0.f);
            v3b[2 * k + 1] = fmaxf(xb.y + b3hi, 0.f);
        }

        u64 h4a[8], h4b[8];
        #pragma unroll
        for (int j = 0; j < 8; j++) { h4a[j] = 0ull; h4b[j] = 0ull; }
        #pragma unroll
        for (int k = 0; k < 32; k++) {
            u64 hha = pack2(v3a[k], v3a[k]);
            u64 hhb = pack2(v3b[k], v3b[k]);
            const ulonglong2* w4r = reinterpret_cast<const ulonglong2*>(&sm[T_W4 + k * 16]);
            #pragma unroll
            for (int j = 0; j < 4; j++) {
                ulonglong2 v = w4r[j];
                h4a[2 * j]     = f2fma(hha, v.x, h4a[2 * j]);
                h4a[2 * j + 1] = f2fma(hha, v.y, h4a[2 * j + 1]);
                h4b[2 * j]     = f2fma(hhb, v.x, h4b[2 * j]);
                h4b[2 * j + 1] = f2fma(hhb, v.y, h4b[2 * j + 1]);
            }
        }
        float v4a[16], v4b[16];
        #pragma unroll
        for (int j = 0; j < 8; j++) {
            float b4lo = sm[T_B4 + 2 * j], b4hi = sm[T_B4 + 2 * j + 1];
            float2 xa = unpack2(h4a[j]);
            float2 xb = unpack2(h4b[j]);
            v4a[2 * j]     = fmaxf(xa.x + b4lo, 0.f);
            v4a[2 * j + 1] = fmaxf(xa.y + b4hi, 0.f);
            v4b[2 * j]     = fmaxf(xb.x + b4lo, 0.f);
            v4b[2 * j + 1] = fmaxf(xb.y + b4hi, 0.f);
        }

        u64 oa0 = 0ull, oa1 = 0ull, ob0 = 0ull, ob1 = 0ull;
        #pragma unroll
        for (int q = 0; q < 16; q++) {
            u64 hha = pack2(v4a[q], v4a[q]);
            u64 hhb = pack2(v4b[q], v4b[q]);
            const ulonglong2* w5r = reinterpret_cast<const ulonglong2*>(&sm[T_W5 + q * 4]);
            ulonglong2 v = w5r[0];
            oa0 = f2fma(hha, v.x, oa0);
            oa1 = f2fma(hha, v.y, oa1);
            ob0 = f2fma(hhb, v.x, ob0);
            ob1 = f2fma(hhb, v.y, ob1);
        }
        float bz0 = sm[T_B5 + 0], bz1 = sm[T_B5 + 1], bz2 = sm[T_B5 + 2];
        {
            float2 xa = unpack2(oa0);
            float2 ya = unpack2(oa1);
            out[3 * p0 + 0] = xa.x + bz0;
            out[3 * p0 + 1] = xa.y + bz1;
            out[3 * p0 + 2] = ya.x + bz2;
        }
        if (has1) {
            float2 xb = unpack2(ob0);
            float2 yb = unpack2(ob1);
            out[3 * p1 + 0] = xb.x + bz0;
            out[3 * p1 + 1] = xb.y + bz1;
            out[3 * p1 + 2] = yb.x + bz2;
        }
    }
}

// ---------------------------------------------------------------------------
extern "C" void kernel_launch(void* const* d_in, const int* in_sizes, int n_in,
                              void* d_out, int out_size) {
    const float* coords = (const float*)d_in[0];
    const float* Bmat   = (const float*)d_in[1];
    const float* L1     = (const float*)d_in[2];
    const float* R1     = (const float*)d_in[3];
    const float* b1     = (const float*)d_in[4];
    const float* L2     = (const float*)d_in[5];
    const float* R2     = (const float*)d_in[6];
    const float* b2     = (const float*)d_in[7];
    const float* W3     = (const float*)d_in[8];
    const float* b3     = (const float*)d_in[9];
    const float* W4     = (const float*)d_in[10];
    const float* b4     = (const float*)d_in[11];
    const float* W5     = (const float*)d_in[12];
    const float* b5     = (const float*)d_in[13];
    float* out = (float*)d_out;

    int npts = in_sizes[0] / 2;
    if (npts > NPTS_C) npts = NPTS_C;

    int dev = 0;
    cudaGetDevice(&dev);
    int sms = 148;
    cudaDeviceGetAttribute(&sms, cudaDevAttrMultiProcessorCount, dev);

    cudaFuncSetAttribute(gff_contract_kernel,
                         cudaFuncAttributeMaxDynamicSharedMemorySize,
                         K1_SMEM * (int)sizeof(float));
    cudaFuncSetAttribute(expand_contract_kernel,
                         cudaFuncAttributeMaxDynamicSharedMemorySize,
                         K2_SMEM * (int)sizeof(float));
    cudaFuncSetAttribute(tail_kernel,
                         cudaFuncAttributeMaxDynamicSharedMemorySize,
                         K3_SMEM * (int)sizeof(float));

    gff_contract_kernel<<<sms, K1_TPB, K1_SMEM * sizeof(float)>>>(
        coords, Bmat, R1, npts);
    expand_contract_kernel<<<sms, K2_TPB, K2_SMEM * sizeof(float)>>>(
        L1, b1, R2, npts);
    tail_kernel<<<sms, K3_TPB, K3_SMEM * sizeof(float)>>>(
        L2, b2, W3, b3, W4, b4, W5, b5, out, npts);
}

// round 10
// speedup vs baseline: 1.0477x; 1.0477x over previous
#include <cuda_runtime.h>
#include <math.h>

// ============================================================================
// 3-kernel ImplicitMLP — recombination of best measured configs:
//  K1: GFF + rank contract warp-tiled GEMM @ TPB=512 (round-9 measured WIN,
//      349us, regs=120, no spill).
//  K2: layer-1 expand GEMM + bias/ReLU/R2 contract @ TPB=384 (round-7/8
//      proven config; round-9's 448 bump regressed ~40us -> reverted).
//  K3: layer-2 expand + dense tail @ TPB=512 (unchanged).
// ============================================================================

#define NPTS_C  524288
#define K1_TPB  512
#define K2_TPB  384
#define K3_TPB  512

typedef unsigned long long u64;

__device__ u64 g_u[40 * (size_t)NPTS_C];   // rank-pair major, point minor
__device__ u64 g_w[5 * (size_t)NPTS_C];    // j-pair major, point minor

__device__ __forceinline__ u64 f2fma(u64 a, u64 b, u64 c) {
    u64 d;
    asm("fma.rn.f32x2 %0, %1, %2, %3;" : "=l"(d) : "l"(a), "l"(b), "l"(c));
    return d;
}
__device__ __forceinline__ u64 f2add(u64 a, u64 b) {
    u64 d;
    asm("add.rn.f32x2 %0, %1, %2;" : "=l"(d) : "l"(a), "l"(b));
    return d;
}
__device__ __forceinline__ u64 pack2(float lo, float hi) {
    u64 r;
    asm("mov.b64 %0, {%1, %2};" : "=l"(r) : "f"(lo), "f"(hi));
    return r;
}
__device__ __forceinline__ float2 unpack2(u64 v) {
    float lo, hi;
    asm("mov.b64 {%0, %1}, %2;" : "=f"(lo), "=f"(hi) : "l"(v));
    return make_float2(lo, hi);
}

// ---------------------------------------------------------------------------
// Kernel 1 (GEMM form): ranks padded to 72 (4 og x 18 = 9 pairs each).
// ---------------------------------------------------------------------------
#define G1_BP   0
#define G1_WR   256
#define G1_OGS  4616                      // 256*18 + 8 skew (bank decorrelate)
#define G1_F    (G1_BP + 256 + 4 * G1_OGS)          // 18720
#define K1_SMEM (G1_F + (K1_TPB / 32) * 1024)       // 18720 + 16384 = 35104 f32

__global__ void __launch_bounds__(K1_TPB, 1) gff_contract_kernel(
    const float* __restrict__ coords, const float* __restrict__ Bmat,
    const float* __restrict__ R1, int npts)
{
    extern __shared__ float sm[];
    const int tid = threadIdx.x;
    const float TWOPI = 6.283185307179586f;

    for (int i = tid; i < 128; i += K1_TPB) {
        sm[G1_BP + 2 * i]     = Bmat[i] * TWOPI;
        sm[G1_BP + 2 * i + 1] = Bmat[128 + i] * TWOPI;
    }
    for (int idx = tid; idx < 4 * 256 * 18; idx += K1_TPB) {
        int og  = idx / 4608;
        int rem = idx - og * 4608;
        int k   = rem / 18;
        int jj  = rem - k * 18;
        int i   = k >> 1;
        int r   = og * 18 + jj;
        float v = 0.f;
        if (r < 70) v = R1[r * 256 + ((k & 1) ? 128 : 0) + i];
        sm[G1_WR + og * G1_OGS + k * 18 + jj] = v;
    }
    __syncthreads();

    const int wid  = tid >> 5;
    const int lane = tid & 31;
    const int pg   = lane & 7;
    const int og   = lane >> 3;
    float* F = &sm[G1_F + wid * 1024];
    const float* wrbase = &sm[G1_WR + og * G1_OGS];

    const int ntiles = npts >> 5;
    const int gw = blockIdx.x * (K1_TPB / 32) + wid;
    const int nw = gridDim.x * (K1_TPB / 32);

    for (int t = gw; t < ntiles; t += nw) {
        const int pt = (t << 5) + lane;
        const int b  = pt >> 12, hw = pt & 4095;
        const float c0 = coords[b * 8192 + hw];
        const float c1 = coords[b * 8192 + 4096 + hw];

        u64 acc[4][9];
        #pragma unroll
        for (int p = 0; p < 4; p++)
            #pragma unroll
            for (int j = 0; j < 9; j++) acc[p][j] = 0ull;

        #pragma unroll 1
        for (int ch = 0; ch < 8; ch++) {
            #pragma unroll
            for (int ii = 0; ii < 16; ii++) {
                float2 bv = reinterpret_cast<const float2*>(&sm[G1_BP])[ch * 16 + ii];
                float pr = fmaf(c0, bv.x, c1 * bv.y);
                float s, c;
                __sincosf(pr, &s, &c);
                F[(2 * ii) * 32 + lane]     = s;
                F[(2 * ii + 1) * 32 + lane] = c;
            }
            __syncwarp();

            const float* wk = &wrbase[(ch * 32) * 18];
            #pragma unroll 2
            for (int kk = 0; kk < 32; kk++) {
                float4 uv = *reinterpret_cast<const float4*>(&F[kk * 32 + pg * 4]);
                const u64* wr = reinterpret_cast<const u64*>(&wk[kk * 18]);
                u64 w0 = wr[0], w1 = wr[1], w2 = wr[2], w3 = wr[3], w4 = wr[4];
                u64 w5 = wr[5], w6 = wr[6], w7 = wr[7], w8 = wr[8];
                u64 d0 = pack2(uv.x, uv.x);
                u64 d1 = pack2(uv.y, uv.y);
                u64 d2 = pack2(uv.z, uv.z);
                u64 d3 = pack2(uv.w, uv.w);
                acc[0][0] = f2fma(d0, w0, acc[0][0]);
                acc[0][1] = f2fma(d0, w1, acc[0][1]);
                acc[0][2] = f2fma(d0, w2, acc[0][2]);
                acc[0][3] = f2fma(d0, w3, acc[0][3]);
                acc[0][4] = f2fma(d0, w4, acc[0][4]);
                acc[0][5] = f2fma(d0, w5, acc[0][5]);
                acc[0][6] = f2fma(d0, w6, acc[0][6]);
                acc[0][7] = f2fma(d0, w7, acc[0][7]);
                acc[0][8] = f2fma(d0, w8, acc[0][8]);
                acc[1][0] = f2fma(d1, w0, acc[1][0]);
                acc[1][1] = f2fma(d1, w1, acc[1][1]);
                acc[1][2] = f2fma(d1, w2, acc[1][2]);
                acc[1][3] = f2fma(d1, w3, acc[1][3]);
                acc[1][4] = f2fma(d1, w4, acc[1][4]);
                acc[1][5] = f2fma(d1, w5, acc[1][5]);
                acc[1][6] = f2fma(d1, w6, acc[1][6]);
                acc[1][7] = f2fma(d1, w7, acc[1][7]);
                acc[1][8] = f2fma(d1, w8, acc[1][8]);
                acc[2][0] = f2fma(d2, w0, acc[2][0]);
                acc[2][1] = f2fma(d2, w1, acc[2][1]);
                acc[2][2] = f2fma(d2, w2, acc[2][2]);
                acc[2][3] = f2fma(d2, w3, acc[2][3]);
                acc[2][4] = f2fma(d2, w4, acc[2][4]);
                acc[2][5] = f2fma(d2, w5, acc[2][5]);
                acc[2][6] = f2fma(d2, w6, acc[2][6]);
                acc[2][7] = f2fma(d2, w7, acc[2][7]);
                acc[2][8] = f2fma(d2, w8, acc[2][8]);
                acc[3][0] = f2fma(d3, w0, acc[3][0]);
                acc[3][1] = f2fma(d3, w1, acc[3][1]);
                acc[3][2] = f2fma(d3, w2, acc[3][2]);
                acc[3][3] = f2fma(d3, w3, acc[3][3]);
                acc[3][4] = f2fma(d3, w4, acc[3][4]);
                acc[3][5] = f2fma(d3, w5, acc[3][5]);
                acc[3][6] = f2fma(d3, w6, acc[3][6]);
                acc[3][7] = f2fma(d3, w7, acc[3][7]);
                acc[3][8] = f2fma(d3, w8, acc[3][8]);
            }
            __syncwarp();
        }

        const int p32 = t << 5;
        #pragma unroll
        for (int j = 0; j < 9; j++) {
            u64* grow = &g_u[(size_t)(og * 9 + j) * NPTS_C + p32 + pg * 4];
            #pragma unroll
            for (int p = 0; p < 4; p++) grow[p] = acc[p][j];
        }
    }
}

// ---------------------------------------------------------------------------
// Kernel 2: layer-1 expand GEMM + bias + ReLU + R2 contract (round-7/8 WIN).
// ---------------------------------------------------------------------------
#define S_L1K 0
#define S_R2  (72 * 256)
#define S_B1  (S_R2 + 256 * 12)
#define S_UT  (S_B1 + 256)
#define K2_SMEM (S_UT + (K2_TPB / 32) * 72 * 32)   // 21760 + 27648 = 49408 f32

__global__ void __launch_bounds__(K2_TPB, 1) expand_contract_kernel(
    const float* __restrict__ L1, const float* __restrict__ b1,
    const float* __restrict__ R2, int npts)
{
    extern __shared__ float sm[];
    const int tid = threadIdx.x;

    for (int idx = tid; idx < 72 * 256; idx += K2_TPB) {
        int k = idx >> 8, o = idx & 255;
        sm[S_L1K + idx] = (k < 70) ? L1[o * 70 + k] : 0.f;
    }
    for (int idx = tid; idx < 256 * 12; idx += K2_TPB) {
        int o = idx / 12, j = idx - o * 12;
        sm[S_R2 + idx] = (j < 10) ? R2[j * 256 + o] : 0.f;
    }
    for (int i = tid; i < 256; i += K2_TPB) sm[S_B1 + i] = b1[i];
    __syncthreads();

    const int wid  = tid >> 5;
    const int lane = tid & 31;
    const int pg   = lane & 7;
    const int og   = lane >> 3;
    float* su = &sm[S_UT + wid * (72 * 32)];

    const int ntiles = npts >> 5;
    const int gw = blockIdx.x * (K2_TPB / 32) + wid;
    const int nw = gridDim.x * (K2_TPB / 32);

    for (int t = gw; t < ntiles; t += nw) {
        const int p32 = t << 5;

        __syncwarp();
        #pragma unroll 4
        for (int rp = 0; rp < 36; rp++) {
            u64 v = g_u[(size_t)rp * NPTS_C + p32 + lane];
            float2 f = unpack2(v);
            su[(2 * rp) * 32 + lane]     = f.x;
            su[(2 * rp + 1) * 32 + lane] = f.y;
        }
        __syncwarp();

        u64 wpart[4][5];
        #pragma unroll
        for (int p = 0; p < 4; p++)
            #pragma unroll
            for (int jp = 0; jp < 5; jp++) wpart[p][jp] = 0ull;

        #pragma unroll 1
        for (int pass = 0; pass < 8; pass++) {
            const int ob = pass * 32 + og * 8;

            u64 acc[4][4];
            #pragma unroll
            for (int p = 0; p < 4; p++)
                #pragma unroll
                for (int op = 0; op < 4; op++) acc[p][op] = 0ull;

            const float* wbase = &sm[S_L1K + ob];
            const float* ubase = &su[pg * 4];

            #pragma unroll 4
            for (int k = 0; k < 72; k++) {
                float4 uv = *reinterpret_cast<const float4*>(&ubase[k * 32]);
                ulonglong2 w01 = *reinterpret_cast<const ulonglong2*>(&wbase[k * 256]);
                ulonglong2 w23 = *reinterpret_cast<const ulonglong2*>(&wbase[k * 256 + 4]);
                u64 d0 = pack2(uv.x, uv.x);
                u64 d1 = pack2(uv.y, uv.y);
                u64 d2 = pack2(uv.z, uv.z);
                u64 d3 = pack2(uv.w, uv.w);
                acc[0][0] = f2fma(d0, w01.x, acc[0][0]);
                acc[0][1] = f2fma(d0, w01.y, acc[0][1]);
                acc[0][2] = f2fma(d0, w23.x, acc[0][2]);
                acc[0][3] = f2fma(d0, w23.y, acc[0][3]);
                acc[1][0] = f2fma(d1, w01.x, acc[1][0]);
                acc[1][1] = f2fma(d1, w01.y, acc[1][1]);
                acc[1][2] = f2fma(d1, w23.x, acc[1][2]);
                acc[1][3] = f2fma(d1, w23.y, acc[1][3]);
                acc[2][0] = f2fma(d2, w01.x, acc[2][0]);
                acc[2][1] = f2fma(d2, w01.y, acc[2][1]);
                acc[2][2] = f2fma(d2, w23.x, acc[2][2]);
                acc[2][3] = f2fma(d2, w23.y, acc[2][3]);
                acc[3][0] = f2fma(d3, w01.x, acc[3][0]);
                acc[3][1] = f2fma(d3, w01.y, acc[3][1]);
                acc[3][2] = f2fma(d3, w23.x, acc[3][2]);
                acc[3][3] = f2fma(d3, w23.y, acc[3][3]);
            }

            const ulonglong2* bp2 = reinterpret_cast<const ulonglong2*>(&sm[S_B1 + ob]);
            ulonglong2 bA = bp2[0], bB = bp2[1];
            u64 bias[4] = { bA.x, bA.y, bB.x, bB.y };

            #pragma unroll
            for (int op = 0; op < 4; op++) {
                const u64* r0 = reinterpret_cast<const u64*>(&sm[S_R2 + (ob + 2 * op) * 12]);
                const u64* r1 = reinterpret_cast<const u64*>(&sm[S_R2 + (ob + 2 * op + 1) * 12]);
                u64 q0[5], q1[5];
                #pragma unroll
                for (int jp = 0; jp < 5; jp++) { q0[jp] = r0[jp]; q1[jp] = r1[jp]; }
                #pragma unroll
                for (int p = 0; p < 4; p++) {
                    float2 h = unpack2(f2add(acc[p][op], bias[op]));
                    float hx = fmaxf(h.x, 0.f);
                    float hy = fmaxf(h.y, 0.f);
                    u64 dx = pack2(hx, hx);
                    u64 dy = pack2(hy, hy);
                    #pragma unroll
                    for (int jp = 0; jp < 5; jp++)
                        wpart[p][jp] = f2fma(dx, q0[jp],
                                       f2fma(dy, q1[jp], wpart[p][jp]));
                }
            }
        }

        #pragma unroll
        for (int p = 0; p < 4; p++)
            #pragma unroll
            for (int jp = 0; jp < 5; jp++) {
                u64 v = wpart[p][jp];
                v = f2add(v, __shfl_xor_sync(0xffffffffu, v, 8));
                v = f2add(v, __shfl_xor_sync(0xffffffffu, v, 16));
                wpart[p][jp] = v;
            }

        const int myp = p32 + pg * 4 + og;
        #pragma unroll
        for (int jp = 0; jp < 5; jp++)
            g_w[(size_t)jp * NPTS_C + myp] = wpart[og][jp];
    }
}

// ---------------------------------------------------------------------------
// Kernel 3: layer-2 expand + dense tail, 2 points/thread (unchanged).
// ---------------------------------------------------------------------------
#define T_L2 0
#define T_W3 (128 * 12)
#define T_W4 (T_W3 + 128 * 32)
#define T_W5 (T_W4 + 32 * 16)
#define T_B2 (T_W5 + 16 * 4)
#define T_B3 (T_B2 + 128)
#define T_B4 (T_B3 + 32)
#define T_B5 (T_B4 + 16)
#define K3_SMEM (T_B5 + 4)

__global__ void __launch_bounds__(K3_TPB, 1) tail_kernel(
    const float* __restrict__ L2, const float* __restrict__ b2,
    const float* __restrict__ W3, const float* __restrict__ b3,
    const float* __restrict__ W4, const float* __restrict__ b4,
    const float* __restrict__ W5, const float* __restrict__ b5,
    float* __restrict__ out, int npts)
{
    extern __shared__ float sm[];
    const int tid = threadIdx.x;

    for (int idx = tid; idx < 128 * 12; idx += K3_TPB) {
        int o = idx / 12, j = idx - o * 12;
        sm[T_L2 + idx] = (j < 10) ? L2[o * 10 + j] : 0.f;
    }
    for (int idx = tid; idx < 128 * 32; idx += K3_TPB) {
        int o = idx / 32, k = idx - o * 32;
        sm[T_W3 + idx] = W3[k * 128 + o];
    }
    for (int idx = tid; idx < 32 * 16; idx += K3_TPB) {
        int k = idx / 16, q = idx - k * 16;
        sm[T_W4 + idx] = W4[q * 32 + k];
    }
    for (int idx = tid; idx < 16 * 4; idx += K3_TPB) {
        int q = idx / 4, c = idx - q * 4;
        sm[T_W5 + idx] = (c < 3) ? W5[c * 16 + q] : 0.f;
    }
    for (int i = tid; i < 128; i += K3_TPB) sm[T_B2 + i] = b2[i];
    for (int i = tid; i < 32;  i += K3_TPB) sm[T_B3 + i] = b3[i];
    for (int i = tid; i < 16;  i += K3_TPB) sm[T_B4 + i] = b4[i];
    if (tid < 4) sm[T_B5 + tid] = (tid < 3) ? b5[tid] : 0.f;
    __syncthreads();

    const int NT = gridDim.x * K3_TPB;
    const int stride2 = 2 * NT;

    for (int p0 = blockIdx.x * K3_TPB + tid; p0 < npts; p0 += stride2) {
        const int p1 = p0 + NT;
        const bool has1 = (p1 < npts);
        const int p1c = has1 ? p1 : p0;

        u64 wa[6], wb[6];
        #pragma unroll
        for (int jp = 0; jp < 5; jp++) {
            wa[jp] = g_w[(size_t)jp * NPTS_C + p0];
            wb[jp] = g_w[(size_t)jp * NPTS_C + p1c];
        }
        wa[5] = 0ull; wb[5] = 0ull;

        u64 h3a[16], h3b[16];
        #pragma unroll
        for (int k = 0; k < 16; k++) { h3a[k] = 0ull; h3b[k] = 0ull; }

        for (int o = 0; o < 128; o++) {
            const ulonglong2* l2r = reinterpret_cast<const ulonglong2*>(&sm[T_L2 + o * 12]);
            ulonglong2 q0 = l2r[0], q1 = l2r[1], q2 = l2r[2];
            u64 aa = f2fma(wa[0], q0.x, 0ull);
            u64 ab = f2fma(wb[0], q0.x, 0ull);
            aa = f2fma(wa[1], q0.y, aa);  ab = f2fma(wb[1], q0.y, ab);
            aa = f2fma(wa[2], q1.x, aa);  ab = f2fma(wb[2], q1.x, ab);
            aa = f2fma(wa[3], q1.y, aa);  ab = f2fma(wb[3], q1.y, ab);
            aa = f2fma(wa[4], q2.x, aa);  ab = f2fma(wb[4], q2.x, ab);
            aa = f2fma(wa[5], q2.y, aa);  ab = f2fma(wb[5], q2.y, ab);
            float bias2 = sm[T_B2 + o];
            float2 va = unpack2(aa);
            float2 vb = unpack2(ab);
            float ha = fmaxf(va.x + va.y + bias2, 0.f);
            float hb = fmaxf(vb.x + vb.y + bias2, 0.f);
            u64 hha = pack2(ha, ha);
            u64 hhb = pack2(hb, hb);
            const ulonglong2* w3r = reinterpret_cast<const ulonglong2*>(&sm[T_W3 + o * 32]);
            #pragma unroll
            for (int k = 0; k < 8; k++) {
                ulonglong2 v = w3r[k];
                h3a[2 * k]     = f2fma(hha, v.x, h3a[2 * k]);
                h3a[2 * k + 1] = f2fma(hha, v.y, h3a[2 * k + 1]);
                h3b[2 * k]     = f2fma(hhb, v.x, h3b[2 * k]);
                h3b[2 * k + 1] = f2fma(hhb, v.y, h3b[2 * k + 1]);
            }
        }

        float v3a[32], v3b[32];
        #pragma unroll
        for (int k = 0; k < 16; k++) {
            float b3lo = sm[T_B3 + 2 * k], b3hi = sm[T_B3 + 2 * k + 1];
            float2 xa = unpack2(h3a[k]);
            float2 xb = unpack2(h3b[k]);
            v3a[2 * k]     = fmaxf(xa.x + b3lo, 0.f);
            v3a[2 * k + 1] = fmaxf(xa.y + b3hi, 0.f);
            v3b[2 * k]     = fmaxf(xb.x + b3lo, 0.f);
            v3b[2 * k + 1] = fmaxf(xb.y + b3hi, 0.f);
        }

        u64 h4a[8], h4b[8];
        #pragma unroll
        for (int j = 0; j < 8; j++) { h4a[j] = 0ull; h4b[j] = 0ull; }
        #pragma unroll
        for (int k = 0; k < 32; k++) {
            u64 hha = pack2(v3a[k], v3a[k]);
            u64 hhb = pack2(v3b[k], v3b[k]);
            const ulonglong2* w4r = reinterpret_cast<const ulonglong2*>(&sm[T_W4 + k * 16]);
            #pragma unroll
            for (int j = 0; j < 4; j++) {
                ulonglong2 v = w4r[j];
                h4a[2 * j]     = f2fma(hha, v.x, h4a[2 * j]);
                h4a[2 * j + 1] = f2fma(hha, v.y, h4a[2 * j + 1]);
                h4b[2 * j]     = f2fma(hhb, v.x, h4b[2 * j]);
                h4b[2 * j + 1] = f2fma(hhb, v.y, h4b[2 * j + 1]);
            }
        }
        float v4a[16], v4b[16];
        #pragma unroll
        for (int j = 0; j < 8; j++) {
            float b4lo = sm[T_B4 + 2 * j], b4hi = sm[T_B4 + 2 * j + 1];
            float2 xa = unpack2(h4a[j]);
            float2 xb = unpack2(h4b[j]);
            v4a[2 * j]     = fmaxf(xa.x + b4lo, 0.f);
            v4a[2 * j + 1] = fmaxf(xa.y + b4hi, 0.f);
            v4b[2 * j]     = fmaxf(xb.x + b4lo, 0.f);
            v4b[2 * j + 1] = fmaxf(xb.y + b4hi, 0.f);
        }

        u64 oa0 = 0ull, oa1 = 0ull, ob0 = 0ull, ob1 = 0ull;
        #pragma unroll
        for (int q = 0; q < 16; q++) {
            u64 hha = pack2(v4a[q], v4a[q]);
            u64 hhb = pack2(v4b[q], v4b[q]);
            const ulonglong2* w5r = reinterpret_cast<const ulonglong2*>(&sm[T_W5 + q * 4]);
            ulonglong2 v = w5r[0];
            oa0 = f2fma(hha, v.x, oa0);
            oa1 = f2fma(hha, v.y, oa1);
            ob0 = f2fma(hhb, v.x, ob0);
            ob1 = f2fma(hhb, v.y, ob1);
        }
        float bz0 = sm[T_B5 + 0], bz1 = sm[T_B5 + 1], bz2 = sm[T_B5 + 2];
        {
            float2 xa = unpack2(oa0);
            float2 ya = unpack2(oa1);
            out[3 * p0 + 0] = xa.x + bz0;
            out[3 * p0 + 1] = xa.y + bz1;
            out[3 * p0 + 2] = ya.x + bz2;
        }
        if (has1) {
            float2 xb = unpack2(ob0);
            float2 yb = unpack2(ob1);
            out[3 * p1 + 0] = xb.x + bz0;
            out[3 * p1 + 1] = xb.y + bz1;
            out[3 * p1 + 2] = yb.x + bz2;
        }
    }
}

// ---------------------------------------------------------------------------
extern "C" void kernel_launch(void* const* d_in, const int* in_sizes, int n_in,
                              void* d_out, int out_size) {
    const float* coords = (const float*)d_in[0];
    const float* Bmat   = (const float*)d_in[1];
    const float* L1     = (const float*)d_in[2];
    const float* R1     = (const float*)d_in[3];
    const float* b1     = (const float*)d_in[4];
    const float* L2     = (const float*)d_in[5];
    const float* R2     = (const float*)d_in[6];
    const float* b2     = (const float*)d_in[7];
    const float* W3     = (const float*)d_in[8];
    const float* b3     = (const float*)d_in[9];
    const float* W4     = (const float*)d_in[10];
    const float* b4     = (const float*)d_in[11];
    const float* W5     = (const float*)d_in[12];
    const float* b5     = (const float*)d_in[13];
    float* out = (float*)d_out;

    int npts = in_sizes[0] / 2;
    if (npts > NPTS_C) npts = NPTS_C;

    int dev = 0;
    cudaGetDevice(&dev);
    int sms = 148;
    cudaDeviceGetAttribute(&sms, cudaDevAttrMultiProcessorCount, dev);

    cudaFuncSetAttribute(gff_contract_kernel,
                         cudaFuncAttributeMaxDynamicSharedMemorySize,
                         K1_SMEM * (int)sizeof(float));
    cudaFuncSetAttribute(expand_contract_kernel,
                         cudaFuncAttributeMaxDynamicSharedMemorySize,
                         K2_SMEM * (int)sizeof(float));
    cudaFuncSetAttribute(tail_kernel,
                         cudaFuncAttributeMaxDynamicSharedMemorySize,
                         K3_SMEM * (int)sizeof(float));

    gff_contract_kernel<<<sms, K1_TPB, K1_SMEM * sizeof(float)>>>(
        coords, Bmat, R1, npts);
    expand_contract_kernel<<<sms, K2_TPB, K2_SMEM * sizeof(float)>>>(
        L1, b1, R2, npts);
    tail_kernel<<<sms, K3_TPB, K3_SMEM * sizeof(float)>>>(
        L2, b2, W3, b3, W4, b4, W5, b5, out, npts);
}